// round 11
// baseline (speedup 1.0000x reference)
#include <cuda_runtime.h>
#include <math.h>
#include <stdint.h>

#define NB     64
#define SHIFT  150
#define LEN    200
#define NH     128
#define MTILE  128
#define NTHR   512
#define NCHUNK 8
#define EPSF   1e-7f
#define HALF_INV_LN10 0.21714724095162588f

#define AS     5290.0f              // signal scale (int16 range / 6.19)
#define BS     32512.0f             // kernel scale (cos=1 -> 32512, split-safe)
#define ACLAMP 6.16f
#define INVS   (1.0f/(5290.0f*32512.0f))

#define FPI    240                  // int8 pitch (bytes): 16B-mult, 60w%32 conflict-free
#define NKS    7                    // 7 k32 steps cover K=224 >= 200 (zero-padded)
#define BHALF  30720                // 128*240 bytes per split array

// smem layout (bytes)
#define SM_AH   0                   // frames hi [128][240] s8
#define SM_AL   30720               // frames lo
#define SM_R1   61440               // pass1 B (hi@+0, lo@+30720); later stash [128][129] f32 (66048)
#define SM_R2   127488              // pass2 B-im (hi/lo)
#define SM_MEAN 193536
#define SM_INV  194048
#define SMEM_TOTAL 194560

__device__ float g_mu[NB];
__device__ float g_sd[NB];
__device__ float g_psum[NB * NCHUNK];
__device__ float g_psq [NB * NCHUNK];
// prepped B: [pass(re,im)][128][240] s8, hi and lo splits
__device__ __align__(16) char g_bh[2 * 128 * FPI];
__device__ __align__(16) char g_bl[2 * 128 * FPI];

__device__ __forceinline__ void imma32(int* d, const uint32_t* a, const uint32_t* bf) {
    asm volatile("mma.sync.aligned.m16n8k32.row.col.s32.s8.s8.s32 "
        "{%0,%1,%2,%3}, {%4,%5,%6,%7}, {%8,%9}, {%0,%1,%2,%3};"
        : "+r"(d[0]), "+r"(d[1]), "+r"(d[2]), "+r"(d[3])
        : "r"(a[0]), "r"(a[1]), "r"(a[2]), "r"(a[3]), "r"(bf[0]), "r"(bf[1]));
}
__device__ __forceinline__ void ldsm4(uint32_t* r, uint32_t addr) {
    asm volatile("ldmatrix.sync.aligned.m8n8.x4.shared.b16 {%0,%1,%2,%3}, [%4];"
        : "=r"(r[0]), "=r"(r[1]), "=r"(r[2]), "=r"(r[3]) : "r"(addr));
}
__device__ __forceinline__ void cpa16(uint32_t dst, const void* src) {
    asm volatile("cp.async.cg.shared.global [%0], [%1], 16;" :: "r"(dst), "l"(src));
}
__device__ __forceinline__ void cpa_commit() {
    asm volatile("cp.async.commit_group;" ::: "memory");
}
template <int N>
__device__ __forceinline__ void cpa_wait() {
    asm volatile("cp.async.wait_group %0;" :: "n"(N) : "memory");
}

// ---------------------------------------------------------------------------
__global__ void __launch_bounds__(256)
stats_partial(const float* __restrict__ x, int S) {
    const int b = blockIdx.x, c = blockIdx.y;
    const int chunk = (S + NCHUNK - 1) / NCHUNK;
    const int s0 = c * chunk;
    const int s1 = min(s0 + chunk, S);
    const float* xb = x + (size_t)b * S + s0;
    const int n = s1 - s0;

    float sum = 0.f, sq = 0.f;
    int pre = (int)(((16u - (unsigned)((size_t)xb & 15u)) & 15u) >> 2);
    if (pre > n) pre = n;
    for (int i = threadIdx.x; i < pre; i += 256) { float v = xb[i]; sum += v; sq += v*v; }
    int n4 = (n - pre) >> 2;
    const float4* x4 = (const float4*)(xb + pre);
    for (int i = threadIdx.x; i < n4; i += 256) {
        float4 v = x4[i];
        sum += v.x + v.y + v.z + v.w;
        sq  += v.x*v.x + v.y*v.y + v.z*v.z + v.w*v.w;
    }
    for (int i = pre + (n4 << 2) + threadIdx.x; i < n; i += 256) { float v = xb[i]; sum += v; sq += v*v; }

    __shared__ float ssum[8], ssq[8];
    #pragma unroll
    for (int o = 16; o > 0; o >>= 1) {
        sum += __shfl_xor_sync(~0u, sum, o);
        sq  += __shfl_xor_sync(~0u, sq,  o);
    }
    int w = threadIdx.x >> 5, ln = threadIdx.x & 31;
    if (ln == 0) { ssum[w] = sum; ssq[w] = sq; }
    __syncthreads();
    if (w == 0 && ln < 8) {
        sum = ssum[ln]; sq = ssq[ln];
        #pragma unroll
        for (int o = 4; o > 0; o >>= 1) {
            sum += __shfl_xor_sync(0xffu, sum, o);
            sq  += __shfl_xor_sync(0xffu, sq,  o);
        }
        if (ln == 0) { g_psum[b*NCHUNK+c] = sum; g_psq[b*NCHUNK+c] = sq; }
    }
}

__global__ void stats_final(int S) {
    int b = threadIdx.x;
    if (b >= NB) return;
    float sum = 0.f, sq = 0.f;
    #pragma unroll
    for (int c = 0; c < NCHUNK; c++) { sum += g_psum[b*NCHUNK+c]; sq += g_psq[b*NCHUNK+c]; }
    float mu  = sum / (float)S;
    float var = sq / (float)S - mu * mu;
    g_mu[b] = mu;
    g_sd[b] = sqrtf(fmaxf(var, 0.f));
}

// ---------------------------------------------------------------------------
// Prep: quantize DFT kernels to int16, split base-256 into two s8.
// ---------------------------------------------------------------------------
__global__ void prep_b_kernel(const float* __restrict__ kr,
                              const float* __restrict__ ki) {
    int idx = blockIdx.x * blockDim.x + threadIdx.x;
    if (idx >= 2 * 128 * FPI) return;
    int kk = idx % FPI;
    int n  = (idx / FPI) & 127;
    int p  = idx / (128 * FPI);
    float v = (kk < LEN) ? (p ? ki : kr)[(size_t)n * LEN + kk] : 0.f;
    int b16 = __float2int_rn(v * BS);
    int bh = (b16 + 128) >> 8;
    int bl = b16 - (bh << 8);
    g_bh[idx] = (char)bh;
    g_bl[idx] = (char)bl;
}

// ---------------------------------------------------------------------------
// Fused: frame+quantize (s8 hi/lo) + 3-term IMMA k32 DFT, two N-passes (re, im)
// grid (25, 64), 512 threads = 16 warps (4m x 4n); warp tile 32t x 32n per pass.
// No barriers inside a pass; B resident whole in smem.
// ---------------------------------------------------------------------------
__global__ void __launch_bounds__(512, 1)
dft_imma_kernel(const float* __restrict__ x,
                float* __restrict__ out, int S, int T) {
    extern __shared__ char smem[];
    const uint32_t smb = (uint32_t)__cvta_generic_to_shared(smem);

    const int tid  = threadIdx.x;
    const int lane = tid & 31;
    const int wid  = tid >> 5;
    const int g    = lane >> 2;
    const int q    = lane & 3;
    const int wm   = wid & 3;
    const int wn   = wid >> 2;
    const int tw   = wm * 32;
    const int nw   = wn * 32;

    const int b  = blockIdx.y;
    const int t0 = blockIdx.x * MTILE;
    const float mu  = g_mu[b];
    const float inv = 1.f / (g_sd[b] + EPSF);
    const float* xrow = x + (size_t)b * S + (size_t)t0 * SHIFT;

    // stream both B passes into smem up-front
    for (int i = tid * 16; i < BHALF; i += NTHR * 16) {
        cpa16(smb + SM_R1 + i, g_bh + i);
        cpa16(smb + SM_R1 + BHALF + i, g_bl + i);
    }
    cpa_commit();
    for (int i = tid * 16; i < BHALF; i += NTHR * 16) {
        cpa16(smb + SM_R2 + i, g_bh + BHALF + i);
        cpa16(smb + SM_R2 + BHALF + i, g_bl + BHALF + i);
    }
    cpa_commit();

    // stage frames: [t][k] quantized int16 -> s8 hi/lo, 4 k per word
    for (int i = tid; i < MTILE * (FPI / 4); i += NTHR) {
        const int t = i / (FPI / 4);
        const int k = (i % (FPI / 4)) * 4;
        uint32_t pa = 0, pl = 0;
        if (k < LEN) {
            const float* src = xrow + t * SHIFT + k;
            #pragma unroll
            for (int j = 0; j < 4; j++) {
                float v = (src[j] - mu) * inv;
                v = fminf(fmaxf(v, -ACLAMP), ACLAMP);
                int a16 = __float2int_rn(v * AS);
                int ah = (a16 + 128) >> 8;
                int al = a16 - (ah << 8);
                pa |= (uint32_t)(ah & 0xFF) << (8 * j);
                pl |= (uint32_t)(al & 0xFF) << (8 * j);
            }
        }
        *(uint32_t*)(smem + SM_AH + t * FPI + k) = pa;
        *(uint32_t*)(smem + SM_AL + t * FPI + k) = pl;
    }

    // ldmatrix per-lane bases
    const uint32_t aAh = smb + SM_AH +
        (uint32_t)((tw + (lane & 15)) * FPI + ((lane >> 4) << 4));
    const uint32_t aAl = aAh + (SM_AL - SM_AH);
    const uint32_t bOff =
        (uint32_t)((((lane & 7) + ((lane >> 4) << 3)) * FPI + (((lane >> 3) & 1) << 4)));

    int hh[2][4][4], mid[2][4][4];
    float* st = (float*)(smem + SM_R1);   // stash overlay after pass 1

    cpa_wait<1>();         // B-re landed
    __syncthreads();       // + frames visible

    #pragma unroll 1
    for (int pass = 0; pass < 2; pass++) {
        #pragma unroll
        for (int mt = 0; mt < 2; mt++)
            #pragma unroll
            for (int u = 0; u < 4; u++)
                #pragma unroll
                for (int e = 0; e < 4; e++) { hh[mt][u][e] = 0; mid[mt][u][e] = 0; }

        const uint32_t bBh = smb + (pass ? SM_R2 : SM_R1) + bOff;
        const uint32_t bBl = bBh + BHALF;

        #pragma unroll
        for (int ks = 0; ks < NKS; ks++) {
            const uint32_t kb = ks * 32;
            uint32_t ah[2][4], al[2][4];
            ldsm4(ah[0], aAh + kb);
            ldsm4(ah[1], aAh + kb + 16 * FPI);
            ldsm4(al[0], aAl + kb);
            ldsm4(al[1], aAl + kb + 16 * FPI);

            uint32_t bh4[2][4], bl4[2][4];
            ldsm4(bh4[0], bBh + (uint32_t)(nw * FPI) + kb);
            ldsm4(bh4[1], bBh + (uint32_t)((nw + 16) * FPI) + kb);
            ldsm4(bl4[0], bBl + (uint32_t)(nw * FPI) + kb);
            ldsm4(bl4[1], bBl + (uint32_t)((nw + 16) * FPI) + kb);

            uint32_t bhf[4][2], blf[4][2];
            #pragma unroll
            for (int u = 0; u < 4; u++) {
                bhf[u][0] = bh4[u >> 1][(u & 1) * 2];
                bhf[u][1] = bh4[u >> 1][(u & 1) * 2 + 1];
                blf[u][0] = bl4[u >> 1][(u & 1) * 2];
                blf[u][1] = bl4[u >> 1][(u & 1) * 2 + 1];
            }
            #pragma unroll
            for (int u = 0; u < 4; u++) {
                imma32(hh[0][u], ah[0], bhf[u]);
                imma32(hh[1][u], ah[1], bhf[u]);
            }
            #pragma unroll
            for (int u = 0; u < 4; u++) {
                imma32(mid[0][u], ah[0], blf[u]);
                imma32(mid[1][u], ah[1], blf[u]);
            }
            #pragma unroll
            for (int u = 0; u < 4; u++) {
                imma32(mid[0][u], al[0], bhf[u]);
                imma32(mid[1][u], al[1], bhf[u]);
            }
        }

        if (pass == 0) {
            cpa_wait<0>();     // B-im landed
            __syncthreads();   // all warps done reading B-re before stash overwrites it
            #pragma unroll
            for (int mt = 0; mt < 2; mt++)
                #pragma unroll
                for (int u = 0; u < 4; u++)
                    #pragma unroll
                    for (int e = 0; e < 4; e++) {
                        const int n = nw + u * 8 + 2 * q + (e & 1);
                        const int t = tw + mt * 16 + g + ((e >> 1) << 3);
                        float r = fmaf(65536.f, (float)hh[mt][u][e],
                                       256.f * (float)mid[mt][u][e]) * INVS;
                        st[n * 129 + t] = r;
                    }
            // no barrier needed: pass2 reads only R2; each (n,t) re-read by its writer
        }
    }

    // pass-2 epilogue: v = log10(|re+imi|), in place
    #pragma unroll
    for (int mt = 0; mt < 2; mt++)
        #pragma unroll
        for (int u = 0; u < 4; u++)
            #pragma unroll
            for (int e = 0; e < 4; e++) {
                const int n = nw + u * 8 + 2 * q + (e & 1);
                const int t = tw + mt * 16 + g + ((e >> 1) << 3);
                float im = fmaf(65536.f, (float)hh[mt][u][e],
                                256.f * (float)mid[mt][u][e]) * INVS;
                float re = st[n * 129 + t];
                float m2 = fmaxf(re * re + im * im, 1e-14f);
                st[n * 129 + t] = __logf(m2) * HALF_INV_LN10;
            }
    __syncthreads();

    float* mn  = (float*)(smem + SM_MEAN);
    float* ivn = (float*)(smem + SM_INV);
    if (tid < MTILE) {
        const int t = tid;
        float sum = 0.f, sq = 0.f;
        #pragma unroll 8
        for (int n = 0; n < NH; n++) {
            float v = st[n * 129 + t];
            sum += v; sq += v * v;
        }
        const float mean = sum * (1.f / NH);
        const float var  = sq * (1.f / NH) - mean * mean;
        mn[t]  = mean;
        ivn[t] = 1.f / (sqrtf(fmaxf(var, 0.f)) + EPSF);
    }
    __syncthreads();
    for (int idx = tid; idx < NH * MTILE; idx += NTHR) {
        const int n = idx >> 7, t = idx & 127;
        out[((size_t)(b * NH + n)) * T + t0 + t] = (st[n * 129 + t] - mn[t]) * ivn[t];
    }
}

// ---------------------------------------------------------------------------
extern "C" void kernel_launch(void* const* d_in, const int* in_sizes, int n_in,
                              void* d_out, int out_size) {
    const float* x  = (const float*)d_in[0];
    const float* kr = (const float*)d_in[1];
    const float* ki = (const float*)d_in[2];
    float* out = (float*)d_out;

    const int S = in_sizes[0] / NB;            // 480050
    const int T = (S - LEN) / SHIFT + 1;       // 3200

    cudaFuncSetAttribute(dft_imma_kernel, cudaFuncAttributeMaxDynamicSharedMemorySize, SMEM_TOTAL);

    stats_partial<<<dim3(NB, NCHUNK), 256>>>(x, S);
    stats_final<<<1, 64>>>(S);
    prep_b_kernel<<<(2 * 128 * FPI + 255) / 256, 256>>>(kr, ki);
    dft_imma_kernel<<<dim3(T / MTILE, NB), NTHR, SMEM_TOTAL>>>(x, out, S, T);
}

// round 12
// speedup vs baseline: 2.7930x; 2.7930x over previous
#include <cuda_runtime.h>
#include <cuda_fp16.h>
#include <math.h>
#include <stdint.h>

#define NB     64
#define SHIFT  150
#define LEN    200
#define NH     128
#define MTILE  64
#define NCHUNK 8
#define EPSF   1e-7f
#define HALF_INV_LN10 0.21714724095162588f

#define FP     200                  // frame pitch (halfs); rows -> banks 4r mod 32
#define BP     56                   // B pitch (halfs); rows -> banks 28r mod 32
#define KC     48                   // K per chunk (3 k16 steps); 48*4 + 16 = 208
#define NCHK   5
#define BCH    28672                // bytes per split chunk: 256*56*2

// per-CTA smem layout (bytes)
#define SM_FH   0                   // frames hi [64][200] half = 25600
#define SM_FL   25600
#define SM_BH   51200               // B chunk hi [256][56] half
#define SM_BL   79872
#define SMEM_TOTAL 108544

// epilogue overlay (over frames region; pitch 68 floats)
#define OFF_V    0                  // [128][68] f32 = 34816
#define OFF_MEAN 34816
#define OFF_INV  35328
#define OFF_PS   35840              // partial sums [2][64]
#define OFF_PQ   36352

__device__ float g_mu[NB];
__device__ float g_sd[NB];
__device__ float g_psum[NB * NCHUNK];
__device__ float g_psq [NB * NCHUNK];
__device__ __align__(16) __half g_bh[NCHK * 256 * BP];
__device__ __align__(16) __half g_bl[NCHK * 256 * BP];

__device__ __forceinline__ void mma16(float* d, const uint32_t* a, const uint32_t* bf) {
    asm volatile("mma.sync.aligned.m16n8k16.row.col.f32.f16.f16.f32 "
        "{%0,%1,%2,%3}, {%4,%5,%6,%7}, {%8,%9}, {%0,%1,%2,%3};"
        : "+f"(d[0]), "+f"(d[1]), "+f"(d[2]), "+f"(d[3])
        : "r"(a[0]), "r"(a[1]), "r"(a[2]), "r"(a[3]), "r"(bf[0]), "r"(bf[1]));
}
__device__ __forceinline__ void ldsm4(uint32_t* r, uint32_t addr) {
    asm volatile("ldmatrix.sync.aligned.m8n8.x4.shared.b16 {%0,%1,%2,%3}, [%4];"
        : "=r"(r[0]), "=r"(r[1]), "=r"(r[2]), "=r"(r[3]) : "r"(addr));
}
__device__ __forceinline__ void cpa16(uint32_t dst, const void* src) {
    asm volatile("cp.async.cg.shared.global [%0], [%1], 16;" :: "r"(dst), "l"(src));
}
__device__ __forceinline__ void cpa_commit() {
    asm volatile("cp.async.commit_group;" ::: "memory");
}
template <int N>
__device__ __forceinline__ void cpa_wait() {
    asm volatile("cp.async.wait_group %0;" :: "n"(N) : "memory");
}

// ---------------------------------------------------------------------------
__global__ void __launch_bounds__(256)
stats_partial(const float* __restrict__ x, int S) {
    const int b = blockIdx.x, c = blockIdx.y;
    const int chunk = (S + NCHUNK - 1) / NCHUNK;
    const int s0 = c * chunk;
    const int s1 = min(s0 + chunk, S);
    const float* xb = x + (size_t)b * S + s0;
    const int n = s1 - s0;

    float sum = 0.f, sq = 0.f;
    int pre = (int)(((16u - (unsigned)((size_t)xb & 15u)) & 15u) >> 2);
    if (pre > n) pre = n;
    for (int i = threadIdx.x; i < pre; i += 256) { float v = xb[i]; sum += v; sq += v*v; }
    int n4 = (n - pre) >> 2;
    const float4* x4 = (const float4*)(xb + pre);
    for (int i = threadIdx.x; i < n4; i += 256) {
        float4 v = x4[i];
        sum += v.x + v.y + v.z + v.w;
        sq  += v.x*v.x + v.y*v.y + v.z*v.z + v.w*v.w;
    }
    for (int i = pre + (n4 << 2) + threadIdx.x; i < n; i += 256) { float v = xb[i]; sum += v; sq += v*v; }

    __shared__ float ssum[8], ssq[8];
    #pragma unroll
    for (int o = 16; o > 0; o >>= 1) {
        sum += __shfl_xor_sync(~0u, sum, o);
        sq  += __shfl_xor_sync(~0u, sq,  o);
    }
    int w = threadIdx.x >> 5, ln = threadIdx.x & 31;
    if (ln == 0) { ssum[w] = sum; ssq[w] = sq; }
    __syncthreads();
    if (w == 0 && ln < 8) {
        sum = ssum[ln]; sq = ssq[ln];
        #pragma unroll
        for (int o = 4; o > 0; o >>= 1) {
            sum += __shfl_xor_sync(0xffu, sum, o);
            sq  += __shfl_xor_sync(0xffu, sq,  o);
        }
        if (ln == 0) { g_psum[b*NCHUNK+c] = sum; g_psq[b*NCHUNK+c] = sq; }
    }
}

__global__ void stats_final(int S) {
    int b = threadIdx.x;
    if (b >= NB) return;
    float sum = 0.f, sq = 0.f;
    #pragma unroll
    for (int c = 0; c < NCHUNK; c++) { sum += g_psum[b*NCHUNK+c]; sq += g_psq[b*NCHUNK+c]; }
    float mu  = sum / (float)S;
    float var = sq / (float)S - mu * mu;
    g_mu[b] = mu;
    g_sd[b] = sqrtf(fmaxf(var, 0.f));
}

// ---------------------------------------------------------------------------
__global__ void prep_b_kernel(const float* __restrict__ kr,
                              const float* __restrict__ ki) {
    int idx = blockIdx.x * blockDim.x + threadIdx.x;
    if (idx >= NCHK * 256 * BP) return;
    int kk = idx % BP;
    int n  = (idx / BP) & 255;
    int c  = idx / (256 * BP);
    int k  = c * KC + kk;
    float v = 0.f;
    if (kk < KC && k < LEN)
        v = ((n < NH) ? kr : ki)[(size_t)(n & 127) * LEN + k];
    __half h = __float2half_rn(v);
    g_bh[idx] = h;
    g_bl[idx] = __float2half_rn(v - __half2float(h));
}

// ---------------------------------------------------------------------------
// Fused: frame+normalize (fp16 hi/lo) + 3xFP16 HMMA DFT
// ldmatrix frags, cp.async B staging, in-warp re/im pairing.
// grid (T/64, NB), 256 threads = 8 warps (2m x 4n); warp tile 32t x 32n(re+im).
// ---------------------------------------------------------------------------
__global__ void __launch_bounds__(256, 2)
dft_mma_kernel(const float* __restrict__ x,
               float* __restrict__ out, int S, int T) {
    extern __shared__ char smem[];
    const uint32_t smb = (uint32_t)__cvta_generic_to_shared(smem);

    const int tid  = threadIdx.x;
    const int lane = tid & 31;
    const int wid  = tid >> 5;
    const int g    = lane >> 2;
    const int q    = lane & 3;
    const int wm   = wid & 1;
    const int wn   = wid >> 1;
    const int tw   = wm * 32;
    const int nw   = wn * 32;

    const int b  = blockIdx.y;
    const int t0 = blockIdx.x * MTILE;
    const float mu  = g_mu[b];
    const float inv = 1.f / (g_sd[b] + EPSF);
    const float* xrow = x + (size_t)b * S + (size_t)t0 * SHIFT;

    // kick off B chunk 0 while frames stage
    for (int i = tid * 16; i < BCH; i += 256 * 16) {
        cpa16(smb + SM_BH + i, (const char*)g_bh + i);
        cpa16(smb + SM_BL + i, (const char*)g_bl + i);
    }
    cpa_commit();

    // stage frames: [t][k] normalized, hi/lo split
    {
        uint32_t* fh = (uint32_t*)(smem + SM_FH);
        uint32_t* fl = (uint32_t*)(smem + SM_FL);
        for (int i = tid; i < MTILE * (FP / 2); i += 256) {
            const int t  = i / (FP / 2);
            const int kp = (i % (FP / 2)) * 2;
            const float* src = xrow + t * SHIFT + kp;
            float v0 = (src[0] - mu) * inv;
            float v1 = (src[1] - mu) * inv;
            __half h0 = __float2half_rn(v0), h1 = __float2half_rn(v1);
            __half l0 = __float2half_rn(v0 - __half2float(h0));
            __half l1 = __float2half_rn(v1 - __half2float(h1));
            fh[i] = (uint32_t)__half_as_ushort(h0) | ((uint32_t)__half_as_ushort(h1) << 16);
            fl[i] = (uint32_t)__half_as_ushort(l0) | ((uint32_t)__half_as_ushort(l1) << 16);
        }
    }

    float acc[2][8][4];
    #pragma unroll
    for (int mt = 0; mt < 2; mt++)
        #pragma unroll
        for (int nt = 0; nt < 8; nt++)
            #pragma unroll
            for (int i = 0; i < 4; i++) acc[mt][nt][i] = 0.f;

    // per-lane ldmatrix bases
    const uint32_t aAh = smb + SM_FH +
        (uint32_t)(((tw + (lane & 15)) * FP + ((lane >> 4) << 3)) * 2);
    const uint32_t aAl = aAh + (SM_FL - SM_FH);
    const uint32_t bOff =
        (uint32_t)((((lane & 7) + ((lane >> 4) << 3)) * BP + ((lane >> 3) & 1) * 8) * 2);

    for (int c = 0; c < NCHK; c++) {
        cpa_wait<0>();
        __syncthreads();

        const uint32_t aBh = smb + SM_BH + bOff;
        const uint32_t aBl = smb + SM_BL + bOff;
        const int nsteps = (c < 4) ? 3 : 1;

        #pragma unroll
        for (int ks = 0; ks < 3; ks++) {
            if (ks >= nsteps) break;
            const uint32_t kgb = (uint32_t)((c * KC + ks * 16) * 2);  // A k offset, bytes
            const uint32_t klb = (uint32_t)((ks * 16) * 2);           // B local k offset

            uint32_t ah[2][4], al[2][4];
            ldsm4(ah[0], aAh + kgb);
            ldsm4(ah[1], aAh + kgb + 16 * FP * 2);
            ldsm4(al[0], aAl + kgb);
            ldsm4(al[1], aAl + kgb + 16 * FP * 2);

            #pragma unroll
            for (int h = 0; h < 2; h++) {     // h=0: re rows n, h=1: im rows n+128
                uint32_t bh4[2][4], bl4[2][4];
                #pragma unroll
                for (int p = 0; p < 2; p++) {
                    const uint32_t noff =
                        (uint32_t)(((h ? 128 : 0) + nw + p * 16) * BP * 2);
                    ldsm4(bh4[p], aBh + noff + klb);
                    ldsm4(bl4[p], aBl + noff + klb);
                }
                uint32_t bhf[4][2], blf[4][2];
                #pragma unroll
                for (int u = 0; u < 4; u++) {
                    bhf[u][0] = bh4[u >> 1][(u & 1) * 2];
                    bhf[u][1] = bh4[u >> 1][(u & 1) * 2 + 1];
                    blf[u][0] = bl4[u >> 1][(u & 1) * 2];
                    blf[u][1] = bl4[u >> 1][(u & 1) * 2 + 1];
                }
                #pragma unroll
                for (int u = 0; u < 4; u++) {
                    mma16(acc[0][h * 4 + u], ah[0], bhf[u]);
                    mma16(acc[1][h * 4 + u], ah[1], bhf[u]);
                }
                #pragma unroll
                for (int u = 0; u < 4; u++) {
                    mma16(acc[0][h * 4 + u], al[0], bhf[u]);
                    mma16(acc[1][h * 4 + u], al[1], bhf[u]);
                }
                #pragma unroll
                for (int u = 0; u < 4; u++) {
                    mma16(acc[0][h * 4 + u], ah[0], blf[u]);
                    mma16(acc[1][h * 4 + u], ah[1], blf[u]);
                }
            }
        }
        __syncthreads();

        // stage next chunk
        if (c < NCHK - 1) {
            const char* sH = (const char*)(g_bh + (c + 1) * 256 * BP);
            const char* sL = (const char*)(g_bl + (c + 1) * 256 * BP);
            for (int i = tid * 16; i < BCH; i += 256 * 16) {
                cpa16(smb + SM_BH + i, sH + i);
                cpa16(smb + SM_BL + i, sL + i);
            }
            cpa_commit();
        }
    }

    // ---- epilogue: thread-local mag/log (re = nt, im = nt+4) ----
    float* vst = (float*)(smem + OFF_V);
    #pragma unroll
    for (int mt = 0; mt < 2; mt++)
        #pragma unroll
        for (int j = 0; j < 4; j++)
            #pragma unroll
            for (int e = 0; e < 4; e++) {
                const int n = nw + j * 8 + 2 * q + (e & 1);
                const int t = tw + mt * 16 + g + ((e >> 1) << 3);
                float re = acc[mt][j][e];
                float im = acc[mt][j + 4][e];
                float m2 = fmaxf(re * re + im * im, 1e-14f);
                vst[n * 68 + t] = __logf(m2) * HALF_INV_LN10;
            }
    __syncthreads();

    float* mn  = (float*)(smem + OFF_MEAN);
    float* ivn = (float*)(smem + OFF_INV);
    float* ps  = (float*)(smem + OFF_PS);
    float* pq  = (float*)(smem + OFF_PQ);
    if (tid < 2 * MTILE) {
        const int t = tid & 63, h = tid >> 6;
        float sum = 0.f, sq = 0.f;
        #pragma unroll 8
        for (int n = h * 64; n < h * 64 + 64; n++) {
            float v = vst[n * 68 + t];
            sum += v; sq += v * v;
        }
        ps[tid] = sum; pq[tid] = sq;
    }
    __syncthreads();
    if (tid < MTILE) {
        const float sum = ps[tid] + ps[tid + 64];
        const float sq  = pq[tid] + pq[tid + 64];
        const float mean = sum * (1.f / NH);
        const float var  = sq * (1.f / NH) - mean * mean;
        mn[tid]  = mean;
        ivn[tid] = 1.f / (sqrtf(fmaxf(var, 0.f)) + EPSF);
    }
    __syncthreads();
    for (int idx = tid; idx < NH * MTILE; idx += 256) {
        const int n = idx >> 6, t = idx & 63;
        out[((size_t)(b * NH + n)) * T + t0 + t] = (vst[n * 68 + t] - mn[t]) * ivn[t];
    }
}

// ---------------------------------------------------------------------------
extern "C" void kernel_launch(void* const* d_in, const int* in_sizes, int n_in,
                              void* d_out, int out_size) {
    const float* x  = (const float*)d_in[0];
    const float* kr = (const float*)d_in[1];
    const float* ki = (const float*)d_in[2];
    float* out = (float*)d_out;

    const int S = in_sizes[0] / NB;            // 480050
    const int T = (S - LEN) / SHIFT + 1;       // 3200

    cudaFuncSetAttribute(dft_mma_kernel, cudaFuncAttributeMaxDynamicSharedMemorySize, SMEM_TOTAL);

    stats_partial<<<dim3(NB, NCHUNK), 256>>>(x, S);
    stats_final<<<1, 64>>>(S);
    prep_b_kernel<<<(NCHK * 256 * BP + 255) / 256, 256>>>(kr, ki);
    dft_mma_kernel<<<dim3(T / MTILE, NB), 256, SMEM_TOTAL>>>(x, out, S, T);
}